// round 9
// baseline (speedup 1.0000x reference)
#include <cuda_runtime.h>
#include <cstdint>

// HistogramOfFeaturesModel on GB300 — R8: software-pipelined rows.
// x:[B,16384] f32, W:[64,257] f32, b:[64] f32 -> out:[B,64] f32
//
// Per CTA (persistent, 6/SM): prologue min/max pass for its first row, then
// per iteration: [pass1(next row): DRAM LDG+minmax] interleaved with
// [pass2(cur row): L2 LDG + conflict-free per-lane-bank u8 binning], then
// per-warp dp4a merge, cross-warp reduce (warps 4-7), 128-dot epilogue
// (warps 0-1, overlaps next iteration's interleaved loop). 2 barriers/row.

#define NF    16384
#define NBINS 128
#define NOUT  64
#define TPB   256

__device__ float g_Wt[NBINS * NOUT];   // [i][o], o contiguous -> coalesced
__device__ float g_S0[NOUT];
__device__ float g_S1[NOUT];

__global__ void prep_kernel(const float* __restrict__ W) {
    const int b = blockIdx.x, tid = threadIdx.x;
    if (b < 32) {
        int e = b * 256 + tid;                 // 32*256 = 8192 entries
        g_Wt[e] = W[(e & 63) * 257 + (e >> 6)];
    } else if (tid < 128) {
        int o = tid >> 1, h = tid & 1;
        float s0 = 0.f, s1 = 0.f;
        for (int j = h; j <= 128; j += 2) {
            float w = W[o * 257 + 128 + j];
            s0 += w;
            s1 += w * ((float)j * 0.0078125f); // t_j = j/128 exact
        }
        s0 += __shfl_xor_sync(0xffffffffu, s0, 1);
        s1 += __shfl_xor_sync(0xffffffffu, s1, 1);
        if (h == 0) { g_S0[o] = s0; g_S1[o] = s1; }
    }
}

__global__ __launch_bounds__(TPB, 6) void hist_feats_kernel(
    const float* __restrict__ x,
    const float* __restrict__ bias,
    float* __restrict__ out,
    int nrows)
{
    __shared__ unsigned int hist32[8 * 1024];   // 32 KB [warp][(b>>2)*32+lane]
    __shared__ unsigned int stage[8 * 128];     // per-warp per-bin counts
    __shared__ float countsf[NBINS];
    __shared__ float S0[NOUT], S1[NOUT], Bs[NOUT];
    __shared__ float wredmin[8], wredmax[8];

    unsigned char* hist8 = reinterpret_cast<unsigned char*>(hist32);

    const int tid = threadIdx.x;
    const int w   = tid >> 5;
    const int l   = tid & 31;
    const int hbase = (w << 12) | (l << 2);     // bank(l) for every bin

    if (tid < NOUT) {
        S0[tid] = g_S0[tid];
        S1[tid] = g_S1[tid];
        Bs[tid] = bias[tid];
    }

    const int stride = gridDim.x;
    int row = blockIdx.x;
    const float4* xc = reinterpret_cast<const float4*>(x) + (size_t)row * (NF / 4);

    // ---------------- prologue: pass 1 for first row ----------------
    float lmin = 3.402823466e38f, lmax = -3.402823466e38f;
    #pragma unroll 4
    for (int j = 0; j < 16; j++) {
        float4 v = xc[j * TPB + tid];
        lmin = fminf(lmin, fminf(fminf(v.x, v.y), fminf(v.z, v.w)));
        lmax = fmaxf(lmax, fmaxf(fmaxf(v.x, v.y), fmaxf(v.z, v.w)));
    }
    #pragma unroll
    for (int off = 16; off > 0; off >>= 1) {
        lmin = fminf(lmin, __shfl_xor_sync(0xffffffffu, lmin, off));
        lmax = fmaxf(lmax, __shfl_xor_sync(0xffffffffu, lmax, off));
    }
    if (l == 0) { wredmin[w] = lmin; wredmax[w] = lmax; }
    __syncthreads();
    float mn_c = wredmin[0], mx_c = wredmax[0];
    #pragma unroll
    for (int k = 1; k < 8; k++) {
        mn_c = fminf(mn_c, wredmin[k]);
        mx_c = fmaxf(mx_c, wredmax[k]);
    }
    float wd_c = mx_c - mn_c;
    float s_c  = 128.f / ((wd_c == 0.f) ? 1.f : wd_c);   // mirrors reference guard
    float o_c  = -mn_c * s_c;                            // bin = floor(fma(v,s,o))
    __syncthreads();   // wred consumed by all before iter-0 rewrites it

    // ---------------- pipelined row loop (2 block barriers/row) ------------
    for (;;) {
        const int nrow = row + stride;
        const bool hn = nrow < nrows;
        const float4* xn = reinterpret_cast<const float4*>(x)
                         + (size_t)(hn ? nrow : row) * (NF / 4);

        // zero own hist region (cross-lane within warp -> syncwarp after)
        {
            uint4 z = make_uint4(0u, 0u, 0u, 0u);
            uint4* h4 = reinterpret_cast<uint4*>(hist8 + (w << 12));
            #pragma unroll
            for (int k = 0; k < 8; k++) h4[(k << 5) + l] = z;
        }
        __syncwarp();

        // ---- interleaved: pass1(next, DRAM) + pass2(cur, L2 + bin) ----
        float nmin = 3.402823466e38f, nmax = -3.402823466e38f;
        #pragma unroll 2
        for (int j = 0; j < 16; j++) {
            if (hn) {
                float4 vn = xn[j * TPB + tid];
                nmin = fminf(nmin, fminf(fminf(vn.x, vn.y), fminf(vn.z, vn.w)));
                nmax = fmaxf(nmax, fmaxf(fmaxf(vn.x, vn.y), fmaxf(vn.z, vn.w)));
            }
            float4 vc = xc[j * TPB + tid];
            int b0 = __float2int_rd(fminf(fmaf(vc.x, s_c, o_c), 127.f));
            int b1 = __float2int_rd(fminf(fmaf(vc.y, s_c, o_c), 127.f));
            int b2 = __float2int_rd(fminf(fmaf(vc.z, s_c, o_c), 127.f));
            int b3 = __float2int_rd(fminf(fmaf(vc.w, s_c, o_c), 127.f));
            b0 = max(b0, 0); b1 = max(b1, 0); b2 = max(b2, 0); b3 = max(b3, 0);
            hist8[hbase + (((b0 & 124) << 5) | (b0 & 3))]++;
            hist8[hbase + (((b1 & 124) << 5) | (b1 & 3))]++;
            hist8[hbase + (((b2 & 124) << 5) | (b2 & 3))]++;
            hist8[hbase + (((b3 & 124) << 5) | (b3 & 3))]++;
        }
        if (hn) {
            #pragma unroll
            for (int off = 16; off > 0; off >>= 1) {
                nmin = fminf(nmin, __shfl_xor_sync(0xffffffffu, nmin, off));
                nmax = fmaxf(nmax, __shfl_xor_sync(0xffffffffu, nmax, off));
            }
            if (l == 0) { wredmin[w] = nmin; wredmax[w] = nmax; }
        }
        __syncwarp();

        // ---- per-warp merge: lane l -> bins 4l..4l+3 (conflict-free c=l^j) ----
        {
            const unsigned int* hw = hist32 + (w << 10) + (l << 5);
            unsigned int a0 = 0, a1 = 0, a2 = 0, a3 = 0;
            #pragma unroll
            for (int j = 0; j < 32; j += 2) {
                unsigned int p = __vadd4(hw[l ^ j], hw[l ^ (j + 1)]); // bytes<=128
                a0 = __dp4a(p, 0x00000001u, a0);
                a1 = __dp4a(p, 0x00000100u, a1);
                a2 = __dp4a(p, 0x00010000u, a2);
                a3 = __dp4a(p, 0x01000000u, a3);
            }
            *reinterpret_cast<uint4*>(&stage[(w << 7) + (l << 2)]) =
                make_uint4(a0, a1, a2, a3);
        }
        __syncthreads();                                   // S2

        // warps 4-7: cross-warp reduce -> normalized counts
        if (tid >= 128) {
            int i = tid - 128;
            unsigned int c = 0;
            #pragma unroll
            for (int ww = 0; ww < 8; ww++) c += stage[(ww << 7) + i];
            countsf[i] = (float)c * (1.f / 16384.f);
        }
        // all threads: next row's scale from wred (written pre-S2)
        float mn_n = 0.f, wd_n = 0.f, s_n = 0.f, o_n = 0.f;
        if (hn) {
            float a = wredmin[0], m = wredmax[0];
            #pragma unroll
            for (int k = 1; k < 8; k++) {
                a = fminf(a, wredmin[k]);
                m = fmaxf(m, wredmax[k]);
            }
            mn_n = a;
            wd_n = m - a;
            s_n  = 128.f / ((wd_n == 0.f) ? 1.f : wd_n);
            o_n  = -mn_n * s_n;
        }
        __syncthreads();                                   // S3

        // warps 0-1: epilogue dot (overlaps next iter's interleave of warps 2-7)
        if (w < 2) {
            int o = (w << 5) | l;
            float a0 = 0.f, a1 = 0.f;
            #pragma unroll 8
            for (int i = 0; i < NBINS; i += 2) {
                a0 += countsf[i]     * g_Wt[i * NOUT + o];
                a1 += countsf[i + 1] * g_Wt[(i + 1) * NOUT + o];
            }
            out[(size_t)row * NOUT + o] =
                a0 + a1 + mn_c * S0[o] + wd_c * S1[o] + Bs[o];
        }

        if (!hn) break;
        row = nrow;
        xc = xn;
        mn_c = mn_n; wd_c = wd_n; s_c = s_n; o_c = o_n;
        // hazards across iterations are ordered by S2/S3 (hist: same-warp program
        // order; stage/countsf/wred: writers passed this row's S2/S3 first).
    }
}

extern "C" void kernel_launch(void* const* d_in, const int* in_sizes, int n_in,
                              void* d_out, int out_size) {
    const float* x = (const float*)d_in[0];
    const float* W = (const float*)d_in[1];
    const float* b = (const float*)d_in[2];
    float* out = (float*)d_out;
    int nrows = in_sizes[0] / NF;

    prep_kernel<<<33, TPB>>>(W);

    int grid = 6 * 148;             // 6 CTAs per SM, persistent
    if (grid > nrows) grid = nrows;
    hist_feats_kernel<<<grid, TPB>>>(x, b, out, nrows);
}

// round 12
// speedup vs baseline: 1.2183x; 1.2183x over previous
#include <cuda_runtime.h>
#include <cstdint>

// HistogramOfFeaturesModel on GB300 — R9: R6 structure, stage aliased into hist
// so SMEM fits 6 CTAs/SM again (R6's 4KB stage pushed 6x(38.2+1)KB past the
// 228KB carveout -> only 5 CTAs resident, occ 50%).
//
// Layout: counter(w,l,b) byte = w*4096 + (b>>2)*128 + l*4 + (b&3) -> bank=l,
// conflict-free for any bin stream. Merge: lane l reads only its own 32-word
// block, then writes its 4 totals back into that block at offset (l&7)*4
// (conflict-free both on store and on the cross-warp reduce read).

#define NF    16384
#define NBINS 128
#define NOUT  64
#define TPB   256

__device__ float g_Wt[NBINS * NOUT];   // [i][o], o contiguous -> coalesced
__device__ float g_S0[NOUT];
__device__ float g_S1[NOUT];

__global__ void prep_kernel(const float* __restrict__ W) {
    const int b = blockIdx.x, tid = threadIdx.x;
    if (b < 32) {
        int e = b * 256 + tid;                 // 32*256 = 8192 entries
        g_Wt[e] = W[(e & 63) * 257 + (e >> 6)];
    } else if (tid < 128) {
        int o = tid >> 1, h = tid & 1;
        float s0 = 0.f, s1 = 0.f;
        for (int j = h; j <= 128; j += 2) {
            float w = W[o * 257 + 128 + j];
            s0 += w;
            s1 += w * ((float)j * 0.0078125f); // t_j = j/128 exact
        }
        s0 += __shfl_xor_sync(0xffffffffu, s0, 1);
        s1 += __shfl_xor_sync(0xffffffffu, s1, 1);
        if (h == 0) { g_S0[o] = s0; g_S1[o] = s1; }
    }
}

__global__ __launch_bounds__(TPB, 6) void hist_feats_kernel(
    const float* __restrict__ x,
    const float* __restrict__ bias,
    float* __restrict__ out,
    int nrows)
{
    __shared__ unsigned int hist32[8 * 1024];   // 32 KB; also hosts merged stage
    __shared__ float part[4 * NOUT];            // 1 KB epilogue partials
    __shared__ float countsf[NBINS];
    __shared__ float S0[NOUT], S1[NOUT], Bs[NOUT];
    __shared__ float wredmin[8], wredmax[8];

    unsigned char* hist8 = reinterpret_cast<unsigned char*>(hist32);

    const int tid = threadIdx.x;
    const int w   = tid >> 5;
    const int l   = tid & 31;
    const int hbase = (w << 12) | (l << 2);     // byte base; bank(l) always

    if (tid < NOUT) {
        S0[tid] = g_S0[tid];
        S1[tid] = g_S1[tid];
        Bs[tid] = bias[tid];
    }
    __syncthreads();

    for (int row = blockIdx.x; row < nrows; row += gridDim.x) {
        const float4* __restrict__ xr =
            reinterpret_cast<const float4*>(x + (size_t)row * NF);

        // zero this warp's own 4KB region (no cross-warp hazard)
        {
            uint4 z = make_uint4(0u, 0u, 0u, 0u);
            uint4* h4 = reinterpret_cast<uint4*>(hist8 + (w << 12));
            #pragma unroll
            for (int k = 0; k < 8; k++) h4[(k << 5) + l] = z;
        }

        // -------- pass 1: min/max (streams row from DRAM) --------
        float lmin = 3.402823466e38f, lmax = -3.402823466e38f;
        #pragma unroll 4
        for (int j = 0; j < 16; j++) {
            float4 v = xr[j * TPB + tid];
            lmin = fminf(lmin, fminf(fminf(v.x, v.y), fminf(v.z, v.w)));
            lmax = fmaxf(lmax, fmaxf(fmaxf(v.x, v.y), fmaxf(v.z, v.w)));
        }
        #pragma unroll
        for (int off = 16; off > 0; off >>= 1) {
            lmin = fminf(lmin, __shfl_xor_sync(0xffffffffu, lmin, off));
            lmax = fmaxf(lmax, __shfl_xor_sync(0xffffffffu, lmax, off));
        }
        if (l == 0) { wredmin[w] = lmin; wredmax[w] = lmax; }
        __syncthreads();                                   // S1 (orders zeroing too)

        float mn = wredmin[0], mx = wredmax[0];
        #pragma unroll
        for (int k = 1; k < 8; k++) {
            mn = fminf(mn, wredmin[k]);
            mx = fmaxf(mx, wredmax[k]);
        }
        float width = mx - mn;
        float s   = 128.f / ((width == 0.f) ? 1.f : width);  // mirrors reference guard
        float off = -mn * s;                                 // bin = floor(fma(v,s,off))

        // -------- pass 2: bin (conflict-free per-lane-bank u8 counters) --------
        #pragma unroll 2
        for (int j = 0; j < 16; j++) {
            float4 v = xr[j * TPB + tid];
            int b0 = __float2int_rd(fminf(fmaf(v.x, s, off), 127.f));
            int b1 = __float2int_rd(fminf(fmaf(v.y, s, off), 127.f));
            int b2 = __float2int_rd(fminf(fmaf(v.z, s, off), 127.f));
            int b3 = __float2int_rd(fminf(fmaf(v.w, s, off), 127.f));
            b0 = max(b0, 0); b1 = max(b1, 0); b2 = max(b2, 0); b3 = max(b3, 0);
            hist8[hbase + (((b0 & 124) << 5) | (b0 & 3))]++;
            hist8[hbase + (((b1 & 124) << 5) | (b1 & 3))]++;
            hist8[hbase + (((b2 & 124) << 5) | (b2 & 3))]++;
            hist8[hbase + (((b3 & 124) << 5) | (b3 & 3))]++;
        }
        __syncwarp();   // region written only by this warp

        // ---- per-warp merge: lane l -> bins 4l..4l+3; reads ONLY its own
        //      32-word block, then writes totals back into that block ----
        {
            const unsigned int* hw = hist32 + (w << 10) + (l << 5);
            unsigned int a0 = 0, a1 = 0, a2 = 0, a3 = 0;
            #pragma unroll
            for (int j = 0; j < 32; j += 2) {
                // column c = l^j: bank c, distinct per lane -> conflict-free
                unsigned int p = __vadd4(hw[l ^ j], hw[l ^ (j + 1)]); // bytes<=128
                a0 = __dp4a(p, 0x00000001u, a0);
                a1 = __dp4a(p, 0x00000100u, a1);
                a2 = __dp4a(p, 0x00010000u, a2);
                a3 = __dp4a(p, 0x01000000u, a3);
            }
            // stage alias: offset (l&7)*4 within own block; banks (l&7)*4+k
            // distinct per quarter-warp -> conflict-free STS.128
            *reinterpret_cast<uint4*>(
                &hist32[(w << 10) + (l << 5) + ((l & 7) << 2)]) =
                make_uint4(a0, a1, a2, a3);
        }
        __syncthreads();                                   // S2

        // cross-warp reduce -> normalized counts (warps 0-3)
        float mnv = mn, wdv = width;   // keep live across barriers
        if (tid < NBINS) {
            int q = tid >> 2;                  // bin quad
            int r = tid & 3;
            int boff = (q << 5) + ((q & 7) << 2) + r;  // bank = q*4+r, distinct
            unsigned int c = 0;
            #pragma unroll
            for (int ww = 0; ww < 8; ww++) c += hist32[(ww << 10) + boff];
            countsf[tid] = (float)c * (1.f / 16384.f);
        }
        __syncthreads();                                   // S3

        // -------- epilogue: out[o] = counts.Wt[:,o] + mn*S0 + width*S1 + b ------
        {
            int o = tid & 63;
            int g = tid >> 6;
            float acc = 0.f;
            int ib = g * 32;
            #pragma unroll 8
            for (int i = 0; i < 32; i++) {
                acc += countsf[ib + i] * g_Wt[(ib + i) * NOUT + o];  // coalesced
            }
            part[(g << 6) + o] = acc;
        }
        __syncthreads();                                   // S4
        if (tid < NOUT) {
            float r = part[tid] + part[64 + tid] + part[128 + tid] + part[192 + tid];
            r += mnv * S0[tid] + wdv * S1[tid] + Bs[tid];
            out[(size_t)row * NOUT + tid] = r;
        }
        // next row's zeroing (after S4) touches only this warp's region; all
        // aliased-stage readers finished at S3.
    }
}

extern "C" void kernel_launch(void* const* d_in, const int* in_sizes, int n_in,
                              void* d_out, int out_size) {
    const float* x = (const float*)d_in[0];
    const float* W = (const float*)d_in[1];
    const float* b = (const float*)d_in[2];
    float* out = (float*)d_out;
    int nrows = in_sizes[0] / NF;

    prep_kernel<<<33, TPB>>>(W);

    int grid = 6 * 148;             // 6 CTAs per SM, persistent
    if (grid > nrows) grid = nrows;
    hist_feats_kernel<<<grid, TPB>>>(x, b, out, nrows);
}

// round 17
// speedup vs baseline: 1.2433x; 1.0205x over previous
#include <cuda_runtime.h>
#include <cstdint>

// HistogramOfFeaturesModel on GB300 — R12: dynamic row stealing + instr diet.
// R9 base (conflict-free per-lane-bank u8 histogram, stage aliased into hist,
// 6 CTAs/SM). New: global-atomic row queue (kills the 8% static tail: 888
// CTAs over 4096 rows left 344 CTAs idle for a whole 19us row), u32-saturate
// CVT (drops max()), LDS.128 rotated merge loads, dual-acc epilogue.

#define NF    16384
#define NBINS 128
#define NOUT  64
#define TPB   256

__device__ float g_Wt[NBINS * NOUT];   // [i][o], o contiguous -> coalesced
__device__ float g_S0[NOUT];
__device__ float g_S1[NOUT];
__device__ unsigned int g_rowctr;

__global__ void prep_kernel(const float* __restrict__ W) {
    const int b = blockIdx.x, tid = threadIdx.x;
    if (b < 32) {
        int e = b * 256 + tid;                 // 32*256 = 8192 entries
        g_Wt[e] = W[(e & 63) * 257 + (e >> 6)];
    } else {
        if (tid == 255) g_rowctr = 0;          // reset work queue every launch
        if (tid < 128) {
            int o = tid >> 1, h = tid & 1;
            float s0 = 0.f, s1 = 0.f;
            for (int j = h; j <= 128; j += 2) {
                float w = W[o * 257 + 128 + j];
                s0 += w;
                s1 += w * ((float)j * 0.0078125f); // t_j = j/128 exact
            }
            s0 += __shfl_xor_sync(0xffffffffu, s0, 1);
            s1 += __shfl_xor_sync(0xffffffffu, s1, 1);
            if (h == 0) { g_S0[o] = s0; g_S1[o] = s1; }
        }
    }
}

__global__ __launch_bounds__(TPB, 6) void hist_feats_kernel(
    const float* __restrict__ x,
    const float* __restrict__ bias,
    float* __restrict__ out,
    int nrows)
{
    __shared__ unsigned int hist32[8 * 1024];   // 32 KB; also hosts merged stage
    __shared__ float part[4 * NOUT];
    __shared__ float countsf[NBINS];
    __shared__ float S0[NOUT], S1[NOUT], Bs[NOUT];
    __shared__ float wredmin[8], wredmax[8];
    __shared__ int srow;

    unsigned char* hist8 = reinterpret_cast<unsigned char*>(hist32);

    const int tid = threadIdx.x;
    const int w   = tid >> 5;
    const int l   = tid & 31;
    const int hbase = (w << 12) | (l << 2);     // byte base; bank(l) always

    if (tid < NOUT) {
        S0[tid] = g_S0[tid];
        S1[tid] = g_S1[tid];
        Bs[tid] = bias[tid];
    }
    if (tid == 0) srow = (int)atomicAdd(&g_rowctr, 1u);
    __syncthreads();                                       // P0

    int row = srow;
    while (row < nrows) {
        const float4* __restrict__ xr =
            reinterpret_cast<const float4*>(x + (size_t)row * NF);

        // zero this warp's own 4KB region (no cross-warp hazard)
        {
            uint4 z = make_uint4(0u, 0u, 0u, 0u);
            uint4* h4 = reinterpret_cast<uint4*>(hist8 + (w << 12));
            #pragma unroll
            for (int k = 0; k < 8; k++) h4[(k << 5) + l] = z;
        }

        // -------- pass 1: min/max (streams row from DRAM) --------
        float lmin = 3.402823466e38f, lmax = -3.402823466e38f;
        #pragma unroll 4
        for (int j = 0; j < 16; j++) {
            float4 v = xr[j * TPB + tid];
            lmin = fminf(lmin, fminf(fminf(v.x, v.y), fminf(v.z, v.w)));
            lmax = fmaxf(lmax, fmaxf(fmaxf(v.x, v.y), fmaxf(v.z, v.w)));
        }
        #pragma unroll
        for (int off = 16; off > 0; off >>= 1) {
            lmin = fminf(lmin, __shfl_xor_sync(0xffffffffu, lmin, off));
            lmax = fmaxf(lmax, __shfl_xor_sync(0xffffffffu, lmax, off));
        }
        if (l == 0) { wredmin[w] = lmin; wredmax[w] = lmax; }
        __syncthreads();                                   // S1 (orders zeroing too)

        float mn = wredmin[0], mx = wredmax[0];
        #pragma unroll
        for (int k = 1; k < 8; k++) {
            mn = fminf(mn, wredmin[k]);
            mx = fmaxf(mx, wredmax[k]);
        }
        float width = mx - mn;
        float s   = 128.f / ((width == 0.f) ? 1.f : width);  // mirrors reference guard
        float off = -mn * s;                                 // bin = floor(fma(v,s,off))

        // -------- pass 2: bin (conflict-free per-lane-bank u8 counters) --------
        // cvt.rmi.u32 saturates negatives to 0 -> no low clamp needed
        #pragma unroll 2
        for (int j = 0; j < 16; j++) {
            float4 v = xr[j * TPB + tid];
            unsigned int b0 = __float2uint_rd(fminf(fmaf(v.x, s, off), 127.f));
            unsigned int b1 = __float2uint_rd(fminf(fmaf(v.y, s, off), 127.f));
            unsigned int b2 = __float2uint_rd(fminf(fmaf(v.z, s, off), 127.f));
            unsigned int b3 = __float2uint_rd(fminf(fmaf(v.w, s, off), 127.f));
            hist8[hbase + (((b0 & 124u) << 5) | (b0 & 3u))]++;
            hist8[hbase + (((b1 & 124u) << 5) | (b1 & 3u))]++;
            hist8[hbase + (((b2 & 124u) << 5) | (b2 & 3u))]++;
            hist8[hbase + (((b3 & 124u) << 5) | (b3 & 3u))]++;
        }
        __syncwarp();   // region written only by this warp

        // ---- per-warp merge: lane l owns bin-quad l (words [32l,32l+32)) ----
        // 8 rotated LDS.128 (conflict-free per quarter-warp phase), two halves
        // of 4 uint4 to cap register pressure; vadd4 pairs (bytes<=128 safe).
        {
            const uint4* blk = reinterpret_cast<const uint4*>(
                hist32 + (w << 10) + (l << 5));
            unsigned int a0 = 0, a1 = 0, a2 = 0, a3 = 0;
            #pragma unroll
            for (int h = 0; h < 2; h++) {
                uint4 qa = blk[(l + 4 * h + 0) & 7];
                uint4 qb = blk[(l + 4 * h + 1) & 7];
                uint4 qc = blk[(l + 4 * h + 2) & 7];
                uint4 qd = blk[(l + 4 * h + 3) & 7];
                unsigned int p;
                p = __vadd4(qa.x, qb.x);
                a0 = __dp4a(p, 0x00000001u, a0); a1 = __dp4a(p, 0x00000100u, a1);
                a2 = __dp4a(p, 0x00010000u, a2); a3 = __dp4a(p, 0x01000000u, a3);
                p = __vadd4(qa.y, qb.y);
                a0 = __dp4a(p, 0x00000001u, a0); a1 = __dp4a(p, 0x00000100u, a1);
                a2 = __dp4a(p, 0x00010000u, a2); a3 = __dp4a(p, 0x01000000u, a3);
                p = __vadd4(qa.z, qb.z);
                a0 = __dp4a(p, 0x00000001u, a0); a1 = __dp4a(p, 0x00000100u, a1);
                a2 = __dp4a(p, 0x00010000u, a2); a3 = __dp4a(p, 0x01000000u, a3);
                p = __vadd4(qa.w, qb.w);
                a0 = __dp4a(p, 0x00000001u, a0); a1 = __dp4a(p, 0x00000100u, a1);
                a2 = __dp4a(p, 0x00010000u, a2); a3 = __dp4a(p, 0x01000000u, a3);
                p = __vadd4(qc.x, qd.x);
                a0 = __dp4a(p, 0x00000001u, a0); a1 = __dp4a(p, 0x00000100u, a1);
                a2 = __dp4a(p, 0x00010000u, a2); a3 = __dp4a(p, 0x01000000u, a3);
                p = __vadd4(qc.y, qd.y);
                a0 = __dp4a(p, 0x00000001u, a0); a1 = __dp4a(p, 0x00000100u, a1);
                a2 = __dp4a(p, 0x00010000u, a2); a3 = __dp4a(p, 0x01000000u, a3);
                p = __vadd4(qc.z, qd.z);
                a0 = __dp4a(p, 0x00000001u, a0); a1 = __dp4a(p, 0x00000100u, a1);
                a2 = __dp4a(p, 0x00010000u, a2); a3 = __dp4a(p, 0x01000000u, a3);
                p = __vadd4(qc.w, qd.w);
                a0 = __dp4a(p, 0x00000001u, a0); a1 = __dp4a(p, 0x00000100u, a1);
                a2 = __dp4a(p, 0x00010000u, a2); a3 = __dp4a(p, 0x01000000u, a3);
            }
            // stage alias: back into own block at offset (l&7)*4 words
            *reinterpret_cast<uint4*>(
                &hist32[(w << 10) + (l << 5) + ((l & 7) << 2)]) =
                make_uint4(a0, a1, a2, a3);
        }

        // prefetch next row id (write ordered before S2; readers read after S4)
        if (tid == 0) srow = (int)atomicAdd(&g_rowctr, 1u);
        __syncthreads();                                   // S2

        // cross-warp reduce -> normalized counts
        float mnv = mn, wdv = width;
        if (tid < NBINS) {
            int q = tid >> 2;
            int r = tid & 3;
            int boff = (q << 5) + ((q & 7) << 2) + r;      // bank = q*4+r distinct
            unsigned int c = 0;
            #pragma unroll
            for (int ww = 0; ww < 8; ww++) c += hist32[(ww << 10) + boff];
            countsf[tid] = (float)c * (1.f / 16384.f);
        }
        __syncthreads();                                   // S3

        // -------- epilogue: out[o] = counts.Wt[:,o] + mn*S0 + width*S1 + b ------
        {
            int o = tid & 63;
            int g = tid >> 6;
            float acc0 = 0.f, acc1 = 0.f;
            int ib = g * 32;
            #pragma unroll 8
            for (int i = 0; i < 32; i += 2) {
                acc0 += countsf[ib + i]     * g_Wt[(ib + i) * NOUT + o];
                acc1 += countsf[ib + i + 1] * g_Wt[(ib + i + 1) * NOUT + o];
            }
            part[(g << 6) + o] = acc0 + acc1;
        }
        __syncthreads();                                   // S4
        if (tid < NOUT) {
            float r = part[tid] + part[64 + tid] + part[128 + tid] + part[192 + tid];
            r += mnv * S0[tid] + wdv * S1[tid] + Bs[tid];
            out[(size_t)row * NOUT + tid] = r;
        }
        row = srow;   // read after S4; next write is after next S1 -> race-free
    }
}

extern "C" void kernel_launch(void* const* d_in, const int* in_sizes, int n_in,
                              void* d_out, int out_size) {
    const float* x = (const float*)d_in[0];
    const float* W = (const float*)d_in[1];
    const float* b = (const float*)d_in[2];
    float* out = (float*)d_out;
    int nrows = in_sizes[0] / NF;

    prep_kernel<<<33, TPB>>>(W);

    int grid = 6 * 148;             // persistent; rows pulled from global queue
    if (grid > nrows) grid = nrows;
    hist_feats_kernel<<<grid, TPB>>>(x, b, out, nrows);
}